// round 1
// baseline (speedup 1.0000x reference)
#include <cuda_runtime.h>

#define NNZ   1000000
#define NROWS 500
#define MCOLS 50000
#define D     128

// ---------------- scratch (device globals; no runtime allocation) ----------
__device__ float g_colmean[MCOLS * D];   // col sums -> means (in place)
__device__ float g_rowsum [NROWS * D];   // raw row sums (for global mean)
__device__ float g_rowmean[NROWS * D];
__device__ float g_G[MCOLS * D];         // 0.25 * colmean @ W_n
__device__ float g_H[NROWS * D];         // 0.25 * rowmean @ W_m
__device__ float g_C[D];                 // 0.25*(gmean@W_both + all biases)
__device__ int   g_colcnt[MCOLS];
__device__ int   g_rowcnt[NROWS];
__device__ int   g_coloff[MCOLS + 1];
__device__ int   g_rowoff[NROWS + 1];
__device__ int   g_colcur[MCOLS];
__device__ int   g_rowcur[NROWS];
__device__ int   g_colids[NNZ];
__device__ int   g_rowids[NNZ];

// ---------------- packed fp32x2 FMA (sm_103a FFMA2 path) -------------------
__device__ __forceinline__ void ffma2(float2& d, const float2 a, const float2 b) {
    asm("fma.rn.f32x2 %0, %1, %2, %0;"
        : "+l"(reinterpret_cast<unsigned long long&>(d))
        : "l"(reinterpret_cast<const unsigned long long&>(const_cast<float2&>(a))),
          "l"(reinterpret_cast<const unsigned long long&>(const_cast<float2&>(b))));
}

// ---------------- phase 0: zero counters -----------------------------------
__global__ void zero_k() {
    int i = blockIdx.x * blockDim.x + threadIdx.x;
    if (i < MCOLS) { g_colcnt[i] = 0; g_colcur[i] = 0; }
    if (i < NROWS) { g_rowcnt[i] = 0; g_rowcur[i] = 0; }
}

// ---------------- phase 1: histogram ---------------------------------------
__global__ void hist_k(const int* __restrict__ row_idx, const int* __restrict__ col_idx) {
    int e = blockIdx.x * blockDim.x + threadIdx.x;
    if (e < NNZ) {
        atomicAdd(&g_colcnt[col_idx[e]], 1);
        atomicAdd(&g_rowcnt[row_idx[e]], 1);
    }
}

// ---------------- phase 2: exclusive scans (single block) ------------------
__global__ void scan_k() {
    __shared__ int s[1024];
    __shared__ int sc;
    int tid = threadIdx.x;
    if (tid == 0) sc = 0;
    __syncthreads();
    // columns
    for (int base = 0; base < MCOLS; base += 1024) {
        int i = base + tid;
        int v = (i < MCOLS) ? g_colcnt[i] : 0;
        s[tid] = v; __syncthreads();
        for (int off = 1; off < 1024; off <<= 1) {
            int t = (tid >= off) ? s[tid - off] : 0;
            __syncthreads();
            s[tid] += t;
            __syncthreads();
        }
        if (i < MCOLS) g_coloff[i] = sc + s[tid] - v;
        __syncthreads();
        if (tid == 0) sc += s[1023];
        __syncthreads();
    }
    if (tid == 0) { g_coloff[MCOLS] = sc; sc = 0; }
    __syncthreads();
    // rows (one chunk)
    {
        int v = (tid < NROWS) ? g_rowcnt[tid] : 0;
        s[tid] = v; __syncthreads();
        for (int off = 1; off < 1024; off <<= 1) {
            int t = (tid >= off) ? s[tid - off] : 0;
            __syncthreads();
            s[tid] += t;
            __syncthreads();
        }
        if (tid < NROWS) g_rowoff[tid] = s[tid] - v;
        if (tid == 0) g_rowoff[NROWS] = s[1023];
    }
}

// ---------------- phase 3: scatter entry ids -------------------------------
__global__ void scatter_k(const int* __restrict__ row_idx, const int* __restrict__ col_idx) {
    int e = blockIdx.x * blockDim.x + threadIdx.x;
    if (e < NNZ) {
        int c = col_idx[e];
        int p = atomicAdd(&g_colcur[c], 1);
        g_colids[g_coloff[c] + p] = e;
        int r = row_idx[e];
        int q = atomicAdd(&g_rowcur[r], 1);
        g_rowids[g_rowoff[r] + q] = e;
    }
}

// ---------------- phase 4: column means (warp per column) ------------------
__global__ void colmean_k(const float* __restrict__ values) {
    int warp = (blockIdx.x * blockDim.x + threadIdx.x) >> 5;
    int lane = threadIdx.x & 31;
    if (warp >= MCOLS) return;
    int beg = g_coloff[warp], end = g_coloff[warp + 1];
    float4 acc = make_float4(0.f, 0.f, 0.f, 0.f);
    for (int j = beg; j < end; j++) {
        int e = g_colids[j];
        float4 v = *(const float4*)(values + (size_t)e * D + lane * 4);
        acc.x += v.x; acc.y += v.y; acc.z += v.z; acc.w += v.w;
    }
    int n = end - beg;
    float inv = 1.0f / (float)(n > 1 ? n : 1);
    acc.x *= inv; acc.y *= inv; acc.z *= inv; acc.w *= inv;
    *(float4*)(g_colmean + (size_t)warp * D + lane * 4) = acc;
}

// ---------------- phase 5: row means (block per row) ------------------------
__global__ void rowmean_k(const float* __restrict__ values) {
    int r = blockIdx.x;
    int lane = threadIdx.x & 31, w = threadIdx.x >> 5;  // 8 warps
    int beg = g_rowoff[r], end = g_rowoff[r + 1];
    float4 acc = make_float4(0.f, 0.f, 0.f, 0.f);
    for (int j = beg + w; j < end; j += 8) {
        int e = g_rowids[j];
        float4 v = *(const float4*)(values + (size_t)e * D + lane * 4);
        acc.x += v.x; acc.y += v.y; acc.z += v.z; acc.w += v.w;
    }
    __shared__ float4 s[8][32];
    s[w][lane] = acc;
    __syncthreads();
    if (w == 0) {
        #pragma unroll
        for (int k = 1; k < 8; k++) {
            float4 t = s[k][lane];
            acc.x += t.x; acc.y += t.y; acc.z += t.z; acc.w += t.w;
        }
        *(float4*)(g_rowsum + (size_t)r * D + lane * 4) = acc;   // raw sum
        int n = end - beg;
        float inv = 1.0f / (float)(n > 1 ? n : 1);
        acc.x *= inv; acc.y *= inv; acc.z *= inv; acc.w *= inv;
        *(float4*)(g_rowmean + (size_t)r * D + lane * 4) = acc;
    }
}

// ---------------- phase 6: global-mean + fused constant --------------------
__global__ void cconst_k(const float* __restrict__ W_both,
                         const float* __restrict__ b_all, const float* __restrict__ b_n,
                         const float* __restrict__ b_m,  const float* __restrict__ b_both) {
    __shared__ float gm[D];
    int t = threadIdx.x;  // 128 threads
    float s = 0.f;
    for (int r = 0; r < NROWS; r++) s += g_rowsum[r * D + t];
    gm[t] = s * (1.0f / (float)NNZ);
    __syncthreads();
    float acc = 0.f;
    for (int k = 0; k < D; k++) acc += gm[k] * W_both[k * D + t];
    g_C[t] = 0.25f * (acc + b_all[t] + b_n[t] + b_m[t] + b_both[t]);
}

// ---------------- phases 7-9: register-tiled SGEMM (128x128 tile, 8x8/thr) --
// out = 0.25*(A @ W)  [+ G[col]+H[row]+C when GATHER]
template <bool GATHER>
__global__ void __launch_bounds__(256, 2)
gemm_k(const float* __restrict__ A, const float* __restrict__ W,
       float* __restrict__ out, int M,
       const int* __restrict__ colidx, const int* __restrict__ rowidx) {
    __shared__ float As[32][132];   // transposed A chunk, padded
    __shared__ float Ws[32][128];
    __shared__ int   s_c[128], s_r[128];
    __shared__ float s_C[128];

    const int tid = threadIdx.x;
    const int m_base = blockIdx.x * 128;

    if (GATHER && tid < 128) {
        int e = m_base + tid;
        if (e >= M) e = M - 1;
        s_c[tid] = colidx[e];
        s_r[tid] = rowidx[e];
        s_C[tid] = g_C[tid];
    }

    float2 acc[8][4];
    #pragma unroll
    for (int i = 0; i < 8; i++)
        #pragma unroll
        for (int j = 0; j < 4; j++) acc[i][j] = make_float2(0.f, 0.f);

    const int tx = tid & 15, ty = tid >> 4;
    const int n0 = tx * 8, m0 = ty * 8;
    const int lm  = tid & 31;   // A loader: m within warp
    const int lk4 = tid >> 5;   // A loader: k-float4 slot (0..7)
    const int wn4 = tid & 31;   // W loader: n-float4 slot
    const int wk  = tid >> 5;   // W loader: k row (0..7), +=8

    for (int kc = 0; kc < 128; kc += 32) {
        #pragma unroll
        for (int it = 0; it < 4; it++) {
            int m = lm + it * 32;
            int row = m_base + m;
            if (row >= M) row = M - 1;
            float4 v = *(const float4*)(A + (size_t)row * 128 + kc + lk4 * 4);
            As[lk4 * 4 + 0][m] = v.x;
            As[lk4 * 4 + 1][m] = v.y;
            As[lk4 * 4 + 2][m] = v.z;
            As[lk4 * 4 + 3][m] = v.w;
        }
        #pragma unroll
        for (int it = 0; it < 4; it++) {
            int k = wk + it * 8;
            *(float4*)&Ws[k][wn4 * 4] = *(const float4*)(W + (size_t)(kc + k) * 128 + wn4 * 4);
        }
        __syncthreads();

        #pragma unroll 8
        for (int k = 0; k < 32; k++) {
            float4 a0 = *(float4*)&As[k][m0];
            float4 a1 = *(float4*)&As[k][m0 + 4];
            float4 b0 = *(float4*)&Ws[k][n0];
            float4 b1 = *(float4*)&Ws[k][n0 + 4];
            float a[8] = {a0.x, a0.y, a0.z, a0.w, a1.x, a1.y, a1.z, a1.w};
            float2 b[4] = {{b0.x, b0.y}, {b0.z, b0.w}, {b1.x, b1.y}, {b1.z, b1.w}};
            #pragma unroll
            for (int i = 0; i < 8; i++) {
                float2 ai = make_float2(a[i], a[i]);
                #pragma unroll
                for (int j = 0; j < 4; j++) ffma2(acc[i][j], ai, b[j]);
            }
        }
        __syncthreads();
    }

    #pragma unroll
    for (int i = 0; i < 8; i++) {
        int m = m0 + i;
        int e = m_base + m;
        if (e >= M) continue;
        float4 o0, o1;
        o0.x = acc[i][0].x * 0.25f; o0.y = acc[i][0].y * 0.25f;
        o0.z = acc[i][1].x * 0.25f; o0.w = acc[i][1].y * 0.25f;
        o1.x = acc[i][2].x * 0.25f; o1.y = acc[i][2].y * 0.25f;
        o1.z = acc[i][3].x * 0.25f; o1.w = acc[i][3].y * 0.25f;
        if (GATHER) {
            int c = s_c[m], r = s_r[m];
            float4 g0 = *(const float4*)(g_G + (size_t)c * 128 + n0);
            float4 g1 = *(const float4*)(g_G + (size_t)c * 128 + n0 + 4);
            float4 h0 = *(const float4*)(g_H + (size_t)r * 128 + n0);
            float4 h1 = *(const float4*)(g_H + (size_t)r * 128 + n0 + 4);
            o0.x += g0.x + h0.x + s_C[n0 + 0];
            o0.y += g0.y + h0.y + s_C[n0 + 1];
            o0.z += g0.z + h0.z + s_C[n0 + 2];
            o0.w += g0.w + h0.w + s_C[n0 + 3];
            o1.x += g1.x + h1.x + s_C[n0 + 4];
            o1.y += g1.y + h1.y + s_C[n0 + 5];
            o1.z += g1.z + h1.z + s_C[n0 + 6];
            o1.w += g1.w + h1.w + s_C[n0 + 7];
        }
        *(float4*)(out + (size_t)e * 128 + n0)     = o0;
        *(float4*)(out + (size_t)e * 128 + n0 + 4) = o1;
    }
}

// ---------------------------------------------------------------------------
extern "C" void kernel_launch(void* const* d_in, const int* in_sizes, int n_in,
                              void* d_out, int out_size) {
    const float* values  = (const float*)d_in[0];
    const int*   row_idx = (const int*)  d_in[1];
    const int*   col_idx = (const int*)  d_in[2];
    const float* W_all   = (const float*)d_in[3];
    // b_all = d_in[4] folded into C
    const float* W_n     = (const float*)d_in[5];
    const float* W_m     = (const float*)d_in[7];
    const float* W_both  = (const float*)d_in[9];
    const float* b_all   = (const float*)d_in[4];
    const float* b_n     = (const float*)d_in[6];
    const float* b_m     = (const float*)d_in[8];
    const float* b_both  = (const float*)d_in[10];
    float* out = (float*)d_out;

    zero_k<<<(MCOLS + 255) / 256, 256>>>();
    hist_k<<<(NNZ + 255) / 256, 256>>>(row_idx, col_idx);
    scan_k<<<1, 1024>>>();
    scatter_k<<<(NNZ + 255) / 256, 256>>>(row_idx, col_idx);
    colmean_k<<<(MCOLS * 32 + 255) / 256, 256>>>(values);
    rowmean_k<<<NROWS, 256>>>(values);
    cconst_k<<<1, 128>>>(W_both, b_all, b_n, b_m, b_both);

    float* colmean_p; cudaGetSymbolAddress((void**)&colmean_p, g_colmean);
    float* rowmean_p; cudaGetSymbolAddress((void**)&rowmean_p, g_rowmean);
    float* G_p;       cudaGetSymbolAddress((void**)&G_p, g_G);
    float* H_p;       cudaGetSymbolAddress((void**)&H_p, g_H);

    gemm_k<false><<<(MCOLS + 127) / 128, 256>>>(colmean_p, W_n, G_p, MCOLS, nullptr, nullptr);
    gemm_k<false><<<(NROWS + 127) / 128, 256>>>(rowmean_p, W_m, H_p, NROWS, nullptr, nullptr);
    gemm_k<true><<<(NNZ + 127) / 128, 256>>>(values, W_all, out, NNZ, col_idx, row_idx);
}

// round 2
// speedup vs baseline: 1.3243x; 1.3243x over previous
#include <cuda_runtime.h>

#define NNZ   1000000
#define NROWS 500
#define MCOLS 50000
#define D     128

// ---------------- scratch (device globals; no runtime allocation) ----------
__device__ float g_colmean[MCOLS * D];
__device__ float g_rowsum [NROWS * D];
__device__ float g_rowmean[NROWS * D];
__device__ float g_G[MCOLS * D];         // 0.25 * colmean @ W_n
__device__ float g_H[NROWS * D];         // 0.25 * rowmean @ W_m
__device__ float g_C[D];                 // 0.25*(gmean@W_both + all biases)
__device__ int   g_colcnt[MCOLS];
__device__ int   g_rowcnt[NROWS];
__device__ int   g_coloff[MCOLS + 1];
__device__ int   g_rowoff[NROWS + 1];
__device__ int   g_colcur[MCOLS];
__device__ int   g_rowcur[NROWS];
__device__ int   g_colids[NNZ];
__device__ int   g_rowids[NNZ];

__device__ __forceinline__ unsigned to_tf32(float f) {
    unsigned u;
    asm("cvt.rna.tf32.f32 %0, %1;" : "=r"(u) : "f"(f));
    return u;
}

// ---------------- phase 0: zero counters -----------------------------------
__global__ void zero_k() {
    int i = blockIdx.x * blockDim.x + threadIdx.x;
    if (i < MCOLS) { g_colcnt[i] = 0; g_colcur[i] = 0; }
    if (i < NROWS) { g_rowcnt[i] = 0; g_rowcur[i] = 0; }
}

// ---------------- phase 1: histogram ---------------------------------------
__global__ void hist_k(const int* __restrict__ row_idx, const int* __restrict__ col_idx) {
    int e = blockIdx.x * blockDim.x + threadIdx.x;
    if (e < NNZ) {
        atomicAdd(&g_colcnt[col_idx[e]], 1);
        atomicAdd(&g_rowcnt[row_idx[e]], 1);
    }
}

// ---------------- phase 2: exclusive scans (single block) ------------------
__global__ void scan_k() {
    __shared__ int s[1024];
    __shared__ int sc;
    int tid = threadIdx.x;
    if (tid == 0) sc = 0;
    __syncthreads();
    for (int base = 0; base < MCOLS; base += 1024) {
        int i = base + tid;
        int v = (i < MCOLS) ? g_colcnt[i] : 0;
        s[tid] = v; __syncthreads();
        for (int off = 1; off < 1024; off <<= 1) {
            int t = (tid >= off) ? s[tid - off] : 0;
            __syncthreads();
            s[tid] += t;
            __syncthreads();
        }
        if (i < MCOLS) g_coloff[i] = sc + s[tid] - v;
        __syncthreads();
        if (tid == 0) sc += s[1023];
        __syncthreads();
    }
    if (tid == 0) { g_coloff[MCOLS] = sc; sc = 0; }
    __syncthreads();
    {
        int v = (tid < NROWS) ? g_rowcnt[tid] : 0;
        s[tid] = v; __syncthreads();
        for (int off = 1; off < 1024; off <<= 1) {
            int t = (tid >= off) ? s[tid - off] : 0;
            __syncthreads();
            s[tid] += t;
            __syncthreads();
        }
        if (tid < NROWS) g_rowoff[tid] = s[tid] - v;
        if (tid == 0) g_rowoff[NROWS] = s[1023];
    }
}

// ---------------- phase 3: scatter entry ids -------------------------------
__global__ void scatter_k(const int* __restrict__ row_idx, const int* __restrict__ col_idx) {
    int e = blockIdx.x * blockDim.x + threadIdx.x;
    if (e < NNZ) {
        int c = col_idx[e];
        int p = atomicAdd(&g_colcur[c], 1);
        g_colids[g_coloff[c] + p] = e;
        int r = row_idx[e];
        int q = atomicAdd(&g_rowcur[r], 1);
        g_rowids[g_rowoff[r] + q] = e;
    }
}

// ---------------- phase 4: column means (warp per column) ------------------
__global__ void colmean_k(const float* __restrict__ values) {
    int warp = (blockIdx.x * blockDim.x + threadIdx.x) >> 5;
    int lane = threadIdx.x & 31;
    if (warp >= MCOLS) return;
    int beg = g_coloff[warp], end = g_coloff[warp + 1];
    float4 acc = make_float4(0.f, 0.f, 0.f, 0.f);
    for (int j = beg; j < end; j++) {
        int e = g_colids[j];
        float4 v = *(const float4*)(values + (size_t)e * D + lane * 4);
        acc.x += v.x; acc.y += v.y; acc.z += v.z; acc.w += v.w;
    }
    int n = end - beg;
    float inv = 1.0f / (float)(n > 1 ? n : 1);
    acc.x *= inv; acc.y *= inv; acc.z *= inv; acc.w *= inv;
    *(float4*)(g_colmean + (size_t)warp * D + lane * 4) = acc;
}

// ---------------- phase 5: row means (block per row) ------------------------
__global__ void rowmean_k(const float* __restrict__ values) {
    int r = blockIdx.x;
    int lane = threadIdx.x & 31, w = threadIdx.x >> 5;  // 8 warps
    int beg = g_rowoff[r], end = g_rowoff[r + 1];
    float4 acc = make_float4(0.f, 0.f, 0.f, 0.f);
    for (int j = beg + w; j < end; j += 8) {
        int e = g_rowids[j];
        float4 v = *(const float4*)(values + (size_t)e * D + lane * 4);
        acc.x += v.x; acc.y += v.y; acc.z += v.z; acc.w += v.w;
    }
    __shared__ float4 s[8][32];
    s[w][lane] = acc;
    __syncthreads();
    if (w == 0) {
        #pragma unroll
        for (int k = 1; k < 8; k++) {
            float4 t = s[k][lane];
            acc.x += t.x; acc.y += t.y; acc.z += t.z; acc.w += t.w;
        }
        *(float4*)(g_rowsum + (size_t)r * D + lane * 4) = acc;
        int n = end - beg;
        float inv = 1.0f / (float)(n > 1 ? n : 1);
        acc.x *= inv; acc.y *= inv; acc.z *= inv; acc.w *= inv;
        *(float4*)(g_rowmean + (size_t)r * D + lane * 4) = acc;
    }
}

// ---------------- phase 6: global-mean + fused constant --------------------
__global__ void cconst_k(const float* __restrict__ W_both,
                         const float* __restrict__ b_all, const float* __restrict__ b_n,
                         const float* __restrict__ b_m,  const float* __restrict__ b_both) {
    __shared__ float gm[D];
    int t = threadIdx.x;
    float s = 0.f;
    for (int r = 0; r < NROWS; r++) s += g_rowsum[r * D + t];
    gm[t] = s * (1.0f / (float)NNZ);
    __syncthreads();
    float acc = 0.f;
    for (int k = 0; k < D; k++) acc += gm[k] * W_both[k * D + t];
    g_C[t] = 0.25f * (acc + b_all[t] + b_n[t] + b_m[t] + b_both[t]);
}

// ---------------- tensor-core GEMM: out = 0.25*(A@W) [+G[col]+H[row]+C] -----
// mma.sync.m16n8k8 tf32. Block tile 128x128, K chunked by 64, 8 warps (4Mx2N),
// each warp: M=32 (2 m16 frags) x N=64 (8 n8 frags). Dynamic smem ~70KB, 2 CTA/SM.
#define AS_STRIDE 68
#define WS_STRIDE 132
#define SMEM_AS   0
#define SMEM_WS   (128 * AS_STRIDE * 4)                 // 34816
#define SMEM_SC   (SMEM_WS + 64 * WS_STRIDE * 4)        // 68608
#define SMEM_IC   (SMEM_SC + 128 * 4)                   // 69120
#define SMEM_IR   (SMEM_IC + 128 * 4)                   // 69632
#define SMEM_TOT  (SMEM_IR + 128 * 4)                   // 70144

__device__ __forceinline__ void mma_tf32(float* c, const unsigned* a, unsigned b0, unsigned b1) {
    asm volatile(
        "mma.sync.aligned.m16n8k8.row.col.f32.tf32.tf32.f32 "
        "{%0,%1,%2,%3}, {%4,%5,%6,%7}, {%8,%9}, {%0,%1,%2,%3};"
        : "+f"(c[0]), "+f"(c[1]), "+f"(c[2]), "+f"(c[3])
        : "r"(a[0]), "r"(a[1]), "r"(a[2]), "r"(a[3]), "r"(b0), "r"(b1));
}

template <bool GATHER>
__global__ void __launch_bounds__(256, 2)
gemm_tc(const float* __restrict__ A, const float* __restrict__ W,
        float* __restrict__ out, int M,
        const int* __restrict__ colidx, const int* __restrict__ rowidx) {
    extern __shared__ char smem[];
    float* As = (float*)(smem + SMEM_AS);   // [128][AS_STRIDE]
    float* Ws = (float*)(smem + SMEM_WS);   // [64][WS_STRIDE]
    float* sC = (float*)(smem + SMEM_SC);
    int*   sc = (int*)  (smem + SMEM_IC);
    int*   sr = (int*)  (smem + SMEM_IR);

    const int tid  = threadIdx.x;
    const int lane = tid & 31;
    const int wid  = tid >> 5;
    const int g    = lane >> 2;    // 0..7
    const int t    = lane & 3;     // 0..3
    const int mw   = (wid & 3) * 32;
    const int nw   = (wid >> 2) * 64;
    const int m_base = blockIdx.x * 128;

    if (GATHER && tid < 128) {
        int e = m_base + tid;
        if (e >= M) e = M - 1;
        sc[tid] = colidx[e];
        sr[tid] = rowidx[e];
        sC[tid] = g_C[tid];
    }

    float acc[2][8][4];
    #pragma unroll
    for (int f = 0; f < 2; f++)
        #pragma unroll
        for (int nf = 0; nf < 8; nf++)
            #pragma unroll
            for (int i = 0; i < 4; i++) acc[f][nf][i] = 0.f;

    for (int kc = 0; kc < 128; kc += 64) {
        // load A chunk [128 m][64 k] -> As, tf32-converted
        #pragma unroll
        for (int it = 0; it < 8; it++) {
            int i = it * 256 + tid;
            int m = i >> 4, kq = i & 15;
            int row = m_base + m;
            if (row >= M) row = M - 1;
            float4 v = *(const float4*)(A + (size_t)row * 128 + kc + kq * 4);
            unsigned* dst = (unsigned*)(As + m * AS_STRIDE + kq * 4);
            dst[0] = to_tf32(v.x); dst[1] = to_tf32(v.y);
            dst[2] = to_tf32(v.z); dst[3] = to_tf32(v.w);
        }
        // load W chunk [64 k][128 n] -> Ws, tf32-converted
        #pragma unroll
        for (int it = 0; it < 8; it++) {
            int i = it * 256 + tid;
            int k = i >> 5, nq = i & 31;
            float4 v = *(const float4*)(W + (size_t)(kc + k) * 128 + nq * 4);
            unsigned* dst = (unsigned*)(Ws + k * WS_STRIDE + nq * 4);
            dst[0] = to_tf32(v.x); dst[1] = to_tf32(v.y);
            dst[2] = to_tf32(v.z); dst[3] = to_tf32(v.w);
        }
        __syncthreads();

        #pragma unroll
        for (int ks = 0; ks < 8; ks++) {
            int k0 = ks * 8;
            unsigned a[2][4];
            #pragma unroll
            for (int f = 0; f < 2; f++) {
                const unsigned* ap = (const unsigned*)(As + (mw + f * 16 + g) * AS_STRIDE + k0 + t);
                const unsigned* ap8 = ap + 8 * AS_STRIDE;
                a[f][0] = ap[0];  a[f][1] = ap8[0];
                a[f][2] = ap[4];  a[f][3] = ap8[4];
            }
            #pragma unroll
            for (int nf = 0; nf < 8; nf++) {
                int n = nw + nf * 8 + g;
                unsigned b0 = *(const unsigned*)(Ws + (k0 + t) * WS_STRIDE + n);
                unsigned b1 = *(const unsigned*)(Ws + (k0 + t + 4) * WS_STRIDE + n);
                mma_tf32(acc[0][nf], a[0], b0, b1);
                mma_tf32(acc[1][nf], a[1], b0, b1);
            }
        }
        __syncthreads();
    }

    // epilogue
    #pragma unroll
    for (int f = 0; f < 2; f++) {
        #pragma unroll
        for (int nf = 0; nf < 8; nf++) {
            int nb = nw + nf * 8 + 2 * t;
            #pragma unroll
            for (int half = 0; half < 2; half++) {
                int m_loc = mw + f * 16 + g + half * 8;
                int e = m_base + m_loc;
                if (e >= M) continue;
                float2 o;
                o.x = acc[f][nf][half * 2 + 0] * 0.25f;
                o.y = acc[f][nf][half * 2 + 1] * 0.25f;
                if (GATHER) {
                    int c = sc[m_loc], r = sr[m_loc];
                    float2 gv = *(const float2*)(g_G + (size_t)c * 128 + nb);
                    float2 hv = *(const float2*)(g_H + (size_t)r * 128 + nb);
                    o.x += gv.x + hv.x + sC[nb];
                    o.y += gv.y + hv.y + sC[nb + 1];
                }
                *(float2*)(out + (size_t)e * 128 + nb) = o;
            }
        }
    }
}

// ---------------------------------------------------------------------------
extern "C" void kernel_launch(void* const* d_in, const int* in_sizes, int n_in,
                              void* d_out, int out_size) {
    const float* values  = (const float*)d_in[0];
    const int*   row_idx = (const int*)  d_in[1];
    const int*   col_idx = (const int*)  d_in[2];
    const float* W_all   = (const float*)d_in[3];
    const float* b_all   = (const float*)d_in[4];
    const float* W_n     = (const float*)d_in[5];
    const float* b_n     = (const float*)d_in[6];
    const float* W_m     = (const float*)d_in[7];
    const float* b_m     = (const float*)d_in[8];
    const float* W_both  = (const float*)d_in[9];
    const float* b_both  = (const float*)d_in[10];
    float* out = (float*)d_out;

    cudaFuncSetAttribute(gemm_tc<false>, cudaFuncAttributeMaxDynamicSharedMemorySize, SMEM_TOT);
    cudaFuncSetAttribute(gemm_tc<true>,  cudaFuncAttributeMaxDynamicSharedMemorySize, SMEM_TOT);

    zero_k<<<(MCOLS + 255) / 256, 256>>>();
    hist_k<<<(NNZ + 255) / 256, 256>>>(row_idx, col_idx);
    scan_k<<<1, 1024>>>();
    scatter_k<<<(NNZ + 255) / 256, 256>>>(row_idx, col_idx);
    colmean_k<<<(MCOLS * 32 + 255) / 256, 256>>>(values);
    rowmean_k<<<NROWS, 256>>>(values);
    cconst_k<<<1, 128>>>(W_both, b_all, b_n, b_m, b_both);

    float* colmean_p; cudaGetSymbolAddress((void**)&colmean_p, g_colmean);
    float* rowmean_p; cudaGetSymbolAddress((void**)&rowmean_p, g_rowmean);
    float* G_p;       cudaGetSymbolAddress((void**)&G_p, g_G);
    float* H_p;       cudaGetSymbolAddress((void**)&H_p, g_H);

    gemm_tc<false><<<(MCOLS + 127) / 128, 256, SMEM_TOT>>>(colmean_p, W_n, G_p, MCOLS, nullptr, nullptr);
    gemm_tc<false><<<(NROWS + 127) / 128, 256, SMEM_TOT>>>(rowmean_p, W_m, H_p, NROWS, nullptr, nullptr);
    gemm_tc<true><<<(NNZ + 127) / 128, 256, SMEM_TOT>>>(values, W_all, out, NNZ, col_idx, row_idx);
}

// round 3
// speedup vs baseline: 1.6942x; 1.2794x over previous
#include <cuda_runtime.h>

#define NNZ   1000000
#define NROWS 500
#define MCOLS 50000
#define D     128

// ---------------- scratch (device globals; no runtime allocation) ----------
__device__ float g_colmean[MCOLS * D];
__device__ float g_rowsum [NROWS * D];
__device__ float g_rowmean[NROWS * D];
__device__ float g_G[MCOLS * D];         // 0.25 * colmean @ W_n
__device__ float g_H[NROWS * D];         // 0.25 * rowmean @ W_m
__device__ float g_C[D];                 // 0.25*(gmean@W_both + all biases)
__device__ int   g_colcnt[MCOLS];
__device__ int   g_rowcnt[NROWS];
__device__ int   g_coloff[MCOLS + 1];
__device__ int   g_rowoff[NROWS + 1];
__device__ int   g_colcur[MCOLS];
__device__ int   g_rowcur[NROWS];
__device__ int   g_colids[NNZ];
__device__ int   g_rowids[NNZ];

__device__ __forceinline__ unsigned to_tf32(float f) {
    unsigned u;
    asm("cvt.rna.tf32.f32 %0, %1;" : "=r"(u) : "f"(f));
    return u;
}

// ---------------- phase 0: zero counters -----------------------------------
__global__ void zero_k() {
    int i = blockIdx.x * blockDim.x + threadIdx.x;
    if (i < MCOLS) { g_colcnt[i] = 0; g_colcur[i] = 0; }
    if (i < NROWS) { g_rowcnt[i] = 0; g_rowcur[i] = 0; }
}

// ---------------- phase 1a: column histogram (global atomics, low contention)
__global__ void hist_col_k(const int* __restrict__ col_idx) {
    int e = blockIdx.x * blockDim.x + threadIdx.x;
    if (e < NNZ) atomicAdd(&g_colcnt[col_idx[e]], 1);
}

// ---------------- phase 1b: row histogram (block-local smem aggregation) ----
__global__ void hist_row_k(const int* __restrict__ row_idx) {  // grid 148
    __shared__ int h[NROWS];
    for (int i = threadIdx.x; i < NROWS; i += blockDim.x) h[i] = 0;
    __syncthreads();
    for (int e = blockIdx.x * blockDim.x + threadIdx.x; e < NNZ;
         e += gridDim.x * blockDim.x)
        atomicAdd(&h[row_idx[e]], 1);
    __syncthreads();
    for (int i = threadIdx.x; i < NROWS; i += blockDim.x) {
        int c = h[i];
        if (c) atomicAdd(&g_rowcnt[i], c);
    }
}

// ---------------- phase 2: fast scans (single block, 1024 threads) ----------
__global__ void scan_k() {
    __shared__ int warpsum[32];
    const int CH = (MCOLS + 1023) / 1024;   // 49
    const int tid = threadIdx.x;
    const int lane = tid & 31, wid = tid >> 5;
    const int base = tid * CH;

    // pass 1: per-thread sum
    int sum = 0;
    for (int i = 0; i < CH; i++) {
        int idx = base + i;
        if (idx < MCOLS) sum += g_colcnt[idx];
    }
    // inclusive warp scan of thread sums
    int s = sum;
    #pragma unroll
    for (int off = 1; off < 32; off <<= 1) {
        int t = __shfl_up_sync(~0u, s, off);
        if (lane >= off) s += t;
    }
    if (lane == 31) warpsum[wid] = s;
    __syncthreads();
    if (wid == 0) {
        int ws = warpsum[lane];
        #pragma unroll
        for (int off = 1; off < 32; off <<= 1) {
            int t = __shfl_up_sync(~0u, ws, off);
            if (lane >= off) ws += t;
        }
        warpsum[lane] = ws;
    }
    __syncthreads();
    int pre = s - sum + (wid > 0 ? warpsum[wid - 1] : 0);
    // pass 2: write prefix
    int run = pre;
    for (int i = 0; i < CH; i++) {
        int idx = base + i;
        if (idx < MCOLS) {
            g_coloff[idx] = run;
            run += g_colcnt[idx];
        }
    }
    if (tid == 1023) g_coloff[MCOLS] = run;
    __syncthreads();

    // row scan (500 elems): smem Hillis-Steele over 512 slots
    __shared__ int rs[512];
    if (tid < 512) rs[tid] = (tid < NROWS) ? g_rowcnt[tid] : 0;
    __syncthreads();
    int v = (tid < 512) ? rs[tid] : 0;
    #pragma unroll
    for (int off = 1; off < 512; off <<= 1) {
        int t = (tid < 512 && tid >= off) ? rs[tid - off] : 0;
        __syncthreads();
        if (tid < 512) rs[tid] = rs[tid] + t;
        __syncthreads();
    }
    if (tid < NROWS) g_rowoff[tid] = rs[tid] - v;
    if (tid == NROWS) g_rowoff[NROWS] = rs[NROWS - 1] + 0;  // tid=500 exists
    if (tid == 0) { }  // no-op
    __syncthreads();
    if (tid == 0) g_rowoff[NROWS] = rs[NROWS - 1];
}

// ---------------- phase 3a: column scatter (global atomics) -----------------
__global__ void scatter_col_k(const int* __restrict__ col_idx) {
    int e = blockIdx.x * blockDim.x + threadIdx.x;
    if (e < NNZ) {
        int c = col_idx[e];
        int p = atomicAdd(&g_colcur[c], 1);
        g_colids[g_coloff[c] + p] = e;
    }
}

// ---------------- phase 3b: row scatter (block-local reservation) -----------
__global__ void scatter_row_k(const int* __restrict__ row_idx) {  // grid 148
    __shared__ int lcnt[NROWS];
    __shared__ int lbase[NROWS];
    const int tid = threadIdx.x;
    const int chunk = (NNZ + gridDim.x - 1) / gridDim.x;
    const int lo = blockIdx.x * chunk;
    const int hi = (lo + chunk < NNZ) ? lo + chunk : NNZ;

    for (int i = tid; i < NROWS; i += blockDim.x) lcnt[i] = 0;
    __syncthreads();
    for (int e = lo + tid; e < hi; e += blockDim.x)
        atomicAdd(&lcnt[row_idx[e]], 1);
    __syncthreads();
    for (int i = tid; i < NROWS; i += blockDim.x) {
        int c = lcnt[i];
        int b = c ? atomicAdd(&g_rowcur[i], c) : 0;
        lbase[i] = g_rowoff[i] + b;
        lcnt[i] = 0;   // reuse as local cursor
    }
    __syncthreads();
    for (int e = lo + tid; e < hi; e += blockDim.x) {
        int r = row_idx[e];
        int slot = atomicAdd(&lcnt[r], 1);
        g_rowids[lbase[r] + slot] = e;
    }
}

// ---------------- phase 4: column means (warp per column) ------------------
__global__ void colmean_k(const float* __restrict__ values) {
    int warp = (blockIdx.x * blockDim.x + threadIdx.x) >> 5;
    int lane = threadIdx.x & 31;
    if (warp >= MCOLS) return;
    int beg = g_coloff[warp], end = g_coloff[warp + 1];
    float4 acc = make_float4(0.f, 0.f, 0.f, 0.f);
    int e = (beg < end) ? g_colids[beg] : 0;
    for (int j = beg; j < end; j++) {
        int e_next = (j + 1 < end) ? g_colids[j + 1] : 0;
        float4 v = *(const float4*)(values + (size_t)e * D + lane * 4);
        acc.x += v.x; acc.y += v.y; acc.z += v.z; acc.w += v.w;
        e = e_next;
    }
    int n = end - beg;
    float inv = 1.0f / (float)(n > 1 ? n : 1);
    acc.x *= inv; acc.y *= inv; acc.z *= inv; acc.w *= inv;
    *(float4*)(g_colmean + (size_t)warp * D + lane * 4) = acc;
}

// ---------------- phase 5: row means (block per row) ------------------------
__global__ void rowmean_k(const float* __restrict__ values) {
    int r = blockIdx.x;
    int lane = threadIdx.x & 31, w = threadIdx.x >> 5;  // 8 warps
    int beg = g_rowoff[r], end = g_rowoff[r + 1];
    float4 acc = make_float4(0.f, 0.f, 0.f, 0.f);
    for (int j = beg + w; j < end; j += 8) {
        int e = g_rowids[j];
        float4 v = *(const float4*)(values + (size_t)e * D + lane * 4);
        acc.x += v.x; acc.y += v.y; acc.z += v.z; acc.w += v.w;
    }
    __shared__ float4 s[8][32];
    s[w][lane] = acc;
    __syncthreads();
    if (w == 0) {
        #pragma unroll
        for (int k = 1; k < 8; k++) {
            float4 t = s[k][lane];
            acc.x += t.x; acc.y += t.y; acc.z += t.z; acc.w += t.w;
        }
        *(float4*)(g_rowsum + (size_t)r * D + lane * 4) = acc;
        int n = end - beg;
        float inv = 1.0f / (float)(n > 1 ? n : 1);
        acc.x *= inv; acc.y *= inv; acc.z *= inv; acc.w *= inv;
        *(float4*)(g_rowmean + (size_t)r * D + lane * 4) = acc;
    }
}

// ---------------- phase 6: global-mean + fused constant --------------------
__global__ void cconst_k(const float* __restrict__ W_both,
                         const float* __restrict__ b_all, const float* __restrict__ b_n,
                         const float* __restrict__ b_m,  const float* __restrict__ b_both) {
    __shared__ float gm[D];
    int t = threadIdx.x;
    float s = 0.f;
    for (int r = 0; r < NROWS; r++) s += g_rowsum[r * D + t];
    gm[t] = s * (1.0f / (float)NNZ);
    __syncthreads();
    float acc = 0.f;
    for (int k = 0; k < D; k++) acc += gm[k] * W_both[k * D + t];
    g_C[t] = 0.25f * (acc + b_all[t] + b_n[t] + b_m[t] + b_both[t]);
}

// ---------------- tensor-core GEMM: out = 0.25*(A@W) [+G[col]+H[row]+C] -----
#define AS_STRIDE 68
#define WS_STRIDE 132
#define SMEM_AS   0
#define SMEM_WS   (128 * AS_STRIDE * 4)
#define SMEM_SC   (SMEM_WS + 64 * WS_STRIDE * 4)
#define SMEM_IC   (SMEM_SC + 128 * 4)
#define SMEM_IR   (SMEM_IC + 128 * 4)
#define SMEM_TOT  (SMEM_IR + 128 * 4)

__device__ __forceinline__ void mma_tf32(float* c, const unsigned* a, unsigned b0, unsigned b1) {
    asm volatile(
        "mma.sync.aligned.m16n8k8.row.col.f32.tf32.tf32.f32 "
        "{%0,%1,%2,%3}, {%4,%5,%6,%7}, {%8,%9}, {%0,%1,%2,%3};"
        : "+f"(c[0]), "+f"(c[1]), "+f"(c[2]), "+f"(c[3])
        : "r"(a[0]), "r"(a[1]), "r"(a[2]), "r"(a[3]), "r"(b0), "r"(b1));
}

template <bool GATHER>
__global__ void __launch_bounds__(256, 2)
gemm_tc(const float* __restrict__ A, const float* __restrict__ W,
        float* __restrict__ out, int M,
        const int* __restrict__ colidx, const int* __restrict__ rowidx) {
    extern __shared__ char smem[];
    float* As = (float*)(smem + SMEM_AS);
    float* Ws = (float*)(smem + SMEM_WS);
    float* sC = (float*)(smem + SMEM_SC);
    int*   sc = (int*)  (smem + SMEM_IC);
    int*   sr = (int*)  (smem + SMEM_IR);

    const int tid  = threadIdx.x;
    const int lane = tid & 31;
    const int wid  = tid >> 5;
    const int g    = lane >> 2;
    const int t    = lane & 3;
    const int mw   = (wid & 3) * 32;
    const int nw   = (wid >> 2) * 64;
    const int m_base = blockIdx.x * 128;

    if (GATHER && tid < 128) {
        int e = m_base + tid;
        if (e >= M) e = M - 1;
        sc[tid] = colidx[e];
        sr[tid] = rowidx[e];
        sC[tid] = g_C[tid];
    }

    float acc[2][8][4];
    #pragma unroll
    for (int f = 0; f < 2; f++)
        #pragma unroll
        for (int nf = 0; nf < 8; nf++)
            #pragma unroll
            for (int i = 0; i < 4; i++) acc[f][nf][i] = 0.f;

    for (int kc = 0; kc < 128; kc += 64) {
        #pragma unroll
        for (int it = 0; it < 8; it++) {
            int i = it * 256 + tid;
            int m = i >> 4, kq = i & 15;
            int row = m_base + m;
            if (row >= M) row = M - 1;
            float4 v = *(const float4*)(A + (size_t)row * 128 + kc + kq * 4);
            unsigned* dst = (unsigned*)(As + m * AS_STRIDE + kq * 4);
            dst[0] = to_tf32(v.x); dst[1] = to_tf32(v.y);
            dst[2] = to_tf32(v.z); dst[3] = to_tf32(v.w);
        }
        #pragma unroll
        for (int it = 0; it < 8; it++) {
            int i = it * 256 + tid;
            int k = i >> 5, nq = i & 31;
            float4 v = *(const float4*)(W + (size_t)(kc + k) * 128 + nq * 4);
            unsigned* dst = (unsigned*)(Ws + k * WS_STRIDE + nq * 4);
            dst[0] = to_tf32(v.x); dst[1] = to_tf32(v.y);
            dst[2] = to_tf32(v.z); dst[3] = to_tf32(v.w);
        }
        __syncthreads();

        #pragma unroll
        for (int ks = 0; ks < 8; ks++) {
            int k0 = ks * 8;
            unsigned a[2][4];
            #pragma unroll
            for (int f = 0; f < 2; f++) {
                const unsigned* ap = (const unsigned*)(As + (mw + f * 16 + g) * AS_STRIDE + k0 + t);
                const unsigned* ap8 = ap + 8 * AS_STRIDE;
                a[f][0] = ap[0];  a[f][1] = ap8[0];
                a[f][2] = ap[4];  a[f][3] = ap8[4];
            }
            #pragma unroll
            for (int nf = 0; nf < 8; nf++) {
                int n = nw + nf * 8 + g;
                unsigned b0 = *(const unsigned*)(Ws + (k0 + t) * WS_STRIDE + n);
                unsigned b1 = *(const unsigned*)(Ws + (k0 + t + 4) * WS_STRIDE + n);
                mma_tf32(acc[0][nf], a[0], b0, b1);
                mma_tf32(acc[1][nf], a[1], b0, b1);
            }
        }
        __syncthreads();
    }

    #pragma unroll
    for (int f = 0; f < 2; f++) {
        #pragma unroll
        for (int nf = 0; nf < 8; nf++) {
            int nb = nw + nf * 8 + 2 * t;
            #pragma unroll
            for (int half = 0; half < 2; half++) {
                int m_loc = mw + f * 16 + g + half * 8;
                int e = m_base + m_loc;
                if (e >= M) continue;
                float2 o;
                o.x = acc[f][nf][half * 2 + 0] * 0.25f;
                o.y = acc[f][nf][half * 2 + 1] * 0.25f;
                if (GATHER) {
                    int c = sc[m_loc], r = sr[m_loc];
                    float2 gv = *(const float2*)(g_G + (size_t)c * 128 + nb);
                    float2 hv = *(const float2*)(g_H + (size_t)r * 128 + nb);
                    o.x += gv.x + hv.x + sC[nb];
                    o.y += gv.y + hv.y + sC[nb + 1];
                }
                *(float2*)(out + (size_t)e * 128 + nb) = o;
            }
        }
    }
}

// ---------------------------------------------------------------------------
extern "C" void kernel_launch(void* const* d_in, const int* in_sizes, int n_in,
                              void* d_out, int out_size) {
    const float* values  = (const float*)d_in[0];
    const int*   row_idx = (const int*)  d_in[1];
    const int*   col_idx = (const int*)  d_in[2];
    const float* W_all   = (const float*)d_in[3];
    const float* b_all   = (const float*)d_in[4];
    const float* W_n     = (const float*)d_in[5];
    const float* b_n     = (const float*)d_in[6];
    const float* W_m     = (const float*)d_in[7];
    const float* b_m     = (const float*)d_in[8];
    const float* W_both  = (const float*)d_in[9];
    const float* b_both  = (const float*)d_in[10];
    float* out = (float*)d_out;

    cudaFuncSetAttribute(gemm_tc<false>, cudaFuncAttributeMaxDynamicSharedMemorySize, SMEM_TOT);
    cudaFuncSetAttribute(gemm_tc<true>,  cudaFuncAttributeMaxDynamicSharedMemorySize, SMEM_TOT);

    zero_k<<<(MCOLS + 255) / 256, 256>>>();
    hist_col_k<<<(NNZ + 255) / 256, 256>>>(col_idx);
    hist_row_k<<<148, 256>>>(row_idx);
    scan_k<<<1, 1024>>>();
    scatter_col_k<<<(NNZ + 255) / 256, 256>>>(col_idx);
    scatter_row_k<<<148, 256>>>(row_idx);
    colmean_k<<<(MCOLS * 32 + 255) / 256, 256>>>(values);
    rowmean_k<<<NROWS, 256>>>(values);
    cconst_k<<<1, 128>>>(W_both, b_all, b_n, b_m, b_both);

    float* colmean_p; cudaGetSymbolAddress((void**)&colmean_p, g_colmean);
    float* rowmean_p; cudaGetSymbolAddress((void**)&rowmean_p, g_rowmean);
    float* G_p;       cudaGetSymbolAddress((void**)&G_p, g_G);
    float* H_p;       cudaGetSymbolAddress((void**)&H_p, g_H);

    gemm_tc<false><<<(MCOLS + 127) / 128, 256, SMEM_TOT>>>(colmean_p, W_n, G_p, MCOLS, nullptr, nullptr);
    gemm_tc<false><<<(NROWS + 127) / 128, 256, SMEM_TOT>>>(rowmean_p, W_m, H_p, NROWS, nullptr, nullptr);
    gemm_tc<true><<<(NNZ + 127) / 128, 256, SMEM_TOT>>>(values, W_all, out, NNZ, col_idx, row_idx);
}

// round 4
// speedup vs baseline: 1.7974x; 1.0609x over previous
#include <cuda_runtime.h>

#define NNZ   1000000
#define NROWS 500
#define MCOLS 50000
#define D     128
#define SCAN_BLOCKS 49   // ceil(50000/1024)

// ---------------- scratch (device globals; no runtime allocation) ----------
__device__ float g_colmean[MCOLS * D];
__device__ float g_rowsum [NROWS * D];
__device__ float g_rowmean[NROWS * D];
__device__ float g_G[MCOLS * D];         // 0.25 * colmean @ W_n
__device__ float g_H[NROWS * D];         // 0.25 * rowmean @ W_m
__device__ float g_C[D];                 // 0.25*(gmean@W_both + all biases)
__device__ int   g_colcnt[MCOLS];
__device__ int   g_rowcnt[NROWS];
__device__ int   g_coloff[MCOLS + 1];
__device__ int   g_rowoff[NROWS + 1];
__device__ int   g_colcur[MCOLS];
__device__ int   g_rowcur[NROWS];
__device__ int   g_colids[NNZ];
__device__ int   g_rowids[NNZ];
__device__ int   g_partial[SCAN_BLOCKS];
__device__ int   g_poff[SCAN_BLOCKS + 1];

__device__ __forceinline__ unsigned to_tf32(float f) {
    unsigned u;
    asm("cvt.rna.tf32.f32 %0, %1;" : "=r"(u) : "f"(f));
    return u;
}

// ---------------- zeroing ----------------------------------------------------
__global__ void zero_col_k() {
    int i = blockIdx.x * blockDim.x + threadIdx.x;
    if (i < MCOLS) { g_colcnt[i] = 0; g_colcur[i] = 0; }
}
__global__ void zero_row_k() {
    int i = threadIdx.x;
    if (i < NROWS) { g_rowcnt[i] = 0; g_rowcur[i] = 0; }
}

// ---------------- histograms -------------------------------------------------
__global__ void hist_col_k(const int* __restrict__ col_idx) {
    int e = blockIdx.x * blockDim.x + threadIdx.x;
    if (e < NNZ) atomicAdd(&g_colcnt[col_idx[e]], 1);
}
__global__ void hist_row_k(const int* __restrict__ row_idx) {  // grid 148
    __shared__ int h[NROWS];
    for (int i = threadIdx.x; i < NROWS; i += blockDim.x) h[i] = 0;
    __syncthreads();
    for (int e = blockIdx.x * blockDim.x + threadIdx.x; e < NNZ;
         e += gridDim.x * blockDim.x)
        atomicAdd(&h[row_idx[e]], 1);
    __syncthreads();
    for (int i = threadIdx.x; i < NROWS; i += blockDim.x) {
        int c = h[i];
        if (c) atomicAdd(&g_rowcnt[i], c);
    }
}

// ---------------- hierarchical column scan -----------------------------------
__global__ void scan1_k() {   // grid SCAN_BLOCKS x 1024: block partial sums
    __shared__ int wsum[32];
    int i = blockIdx.x * 1024 + threadIdx.x;
    int lane = threadIdx.x & 31, wid = threadIdx.x >> 5;
    int v = (i < MCOLS) ? g_colcnt[i] : 0;
    #pragma unroll
    for (int off = 16; off > 0; off >>= 1) v += __shfl_down_sync(~0u, v, off);
    if (lane == 0) wsum[wid] = v;
    __syncthreads();
    if (wid == 0) {
        int s = wsum[lane];
        #pragma unroll
        for (int off = 16; off > 0; off >>= 1) s += __shfl_down_sync(~0u, s, off);
        if (lane == 0) g_partial[blockIdx.x] = s;
    }
}

// generic small exclusive scan: n <= 1024, out[n] = total
__global__ void small_scan_k(const int* __restrict__ in, int* __restrict__ out, int n) {
    __shared__ int wsum[32];
    int tid = threadIdx.x, lane = tid & 31, wid = tid >> 5;
    int v = (tid < n) ? in[tid] : 0;
    int s = v;
    #pragma unroll
    for (int off = 1; off < 32; off <<= 1) {
        int t = __shfl_up_sync(~0u, s, off);
        if (lane >= off) s += t;
    }
    if (lane == 31) wsum[wid] = s;
    __syncthreads();
    if (wid == 0) {
        int ws = wsum[lane];
        #pragma unroll
        for (int off = 1; off < 32; off <<= 1) {
            int t = __shfl_up_sync(~0u, ws, off);
            if (lane >= off) ws += t;
        }
        wsum[lane] = ws;
    }
    __syncthreads();
    int excl = s - v + (wid > 0 ? wsum[wid - 1] : 0);
    if (tid < n) out[tid] = excl;
    if (tid == n - 1) out[n] = excl + v;
}

__global__ void scan3_k() {   // grid SCAN_BLOCKS x 1024: final col offsets
    __shared__ int wsum[32];
    int i = blockIdx.x * 1024 + threadIdx.x;
    int lane = threadIdx.x & 31, wid = threadIdx.x >> 5;
    int v = (i < MCOLS) ? g_colcnt[i] : 0;
    int s = v;
    #pragma unroll
    for (int off = 1; off < 32; off <<= 1) {
        int t = __shfl_up_sync(~0u, s, off);
        if (lane >= off) s += t;
    }
    if (lane == 31) wsum[wid] = s;
    __syncthreads();
    if (wid == 0) {
        int ws = wsum[lane];
        #pragma unroll
        for (int off = 1; off < 32; off <<= 1) {
            int t = __shfl_up_sync(~0u, ws, off);
            if (lane >= off) ws += t;
        }
        wsum[lane] = ws;
    }
    __syncthreads();
    int excl = s - v + (wid > 0 ? wsum[wid - 1] : 0) + g_poff[blockIdx.x];
    if (i < MCOLS) g_coloff[i] = excl;
    if (i == MCOLS - 1) g_coloff[MCOLS] = excl + v;
}

// ---------------- scatters ---------------------------------------------------
__global__ void scatter_col_k(const int* __restrict__ col_idx) {
    int e = blockIdx.x * blockDim.x + threadIdx.x;
    if (e < NNZ) {
        int c = col_idx[e];
        int p = atomicAdd(&g_colcur[c], 1);
        g_colids[g_coloff[c] + p] = e;
    }
}
__global__ void scatter_row_k(const int* __restrict__ row_idx) {  // grid 148
    __shared__ int lcnt[NROWS];
    __shared__ int lbase[NROWS];
    const int tid = threadIdx.x;
    const int chunk = (NNZ + gridDim.x - 1) / gridDim.x;
    const int lo = blockIdx.x * chunk;
    const int hi = (lo + chunk < NNZ) ? lo + chunk : NNZ;

    for (int i = tid; i < NROWS; i += blockDim.x) lcnt[i] = 0;
    __syncthreads();
    for (int e = lo + tid; e < hi; e += blockDim.x)
        atomicAdd(&lcnt[row_idx[e]], 1);
    __syncthreads();
    for (int i = tid; i < NROWS; i += blockDim.x) {
        int c = lcnt[i];
        int b = c ? atomicAdd(&g_rowcur[i], c) : 0;
        lbase[i] = g_rowoff[i] + b;
        lcnt[i] = 0;
    }
    __syncthreads();
    for (int e = lo + tid; e < hi; e += blockDim.x) {
        int r = row_idx[e];
        int slot = atomicAdd(&lcnt[r], 1);
        g_rowids[lbase[r] + slot] = e;
    }
}

// ---------------- means ------------------------------------------------------
__global__ void colmean_k(const float* __restrict__ values) {
    int warp = (blockIdx.x * blockDim.x + threadIdx.x) >> 5;
    int lane = threadIdx.x & 31;
    if (warp >= MCOLS) return;
    int beg = g_coloff[warp], end = g_coloff[warp + 1];
    float4 acc = make_float4(0.f, 0.f, 0.f, 0.f);
    int e = (beg < end) ? g_colids[beg] : 0;
    for (int j = beg; j < end; j++) {
        int e_next = (j + 1 < end) ? g_colids[j + 1] : 0;
        float4 v = *(const float4*)(values + (size_t)e * D + lane * 4);
        acc.x += v.x; acc.y += v.y; acc.z += v.z; acc.w += v.w;
        e = e_next;
    }
    int n = end - beg;
    float inv = 1.0f / (float)(n > 1 ? n : 1);
    acc.x *= inv; acc.y *= inv; acc.z *= inv; acc.w *= inv;
    *(float4*)(g_colmean + (size_t)warp * D + lane * 4) = acc;
}

__global__ void rowmean_k(const float* __restrict__ values) {
    int r = blockIdx.x;
    int lane = threadIdx.x & 31, w = threadIdx.x >> 5;  // 8 warps
    int beg = g_rowoff[r], end = g_rowoff[r + 1];
    float4 acc = make_float4(0.f, 0.f, 0.f, 0.f);
    for (int j = beg + w; j < end; j += 8) {
        int e = g_rowids[j];
        float4 v = *(const float4*)(values + (size_t)e * D + lane * 4);
        acc.x += v.x; acc.y += v.y; acc.z += v.z; acc.w += v.w;
    }
    __shared__ float4 s[8][32];
    s[w][lane] = acc;
    __syncthreads();
    if (w == 0) {
        #pragma unroll
        for (int k = 1; k < 8; k++) {
            float4 t = s[k][lane];
            acc.x += t.x; acc.y += t.y; acc.z += t.z; acc.w += t.w;
        }
        *(float4*)(g_rowsum + (size_t)r * D + lane * 4) = acc;
        int n = end - beg;
        float inv = 1.0f / (float)(n > 1 ? n : 1);
        acc.x *= inv; acc.y *= inv; acc.z *= inv; acc.w *= inv;
        *(float4*)(g_rowmean + (size_t)r * D + lane * 4) = acc;
    }
}

// ---------------- global-mean + fused constant -------------------------------
__global__ void cconst_k(const float* __restrict__ W_both,
                         const float* __restrict__ b_all, const float* __restrict__ b_n,
                         const float* __restrict__ b_m,  const float* __restrict__ b_both) {
    __shared__ float gm[D];
    int t = threadIdx.x;
    float s = 0.f;
    for (int r = 0; r < NROWS; r++) s += g_rowsum[r * D + t];
    gm[t] = s * (1.0f / (float)NNZ);
    __syncthreads();
    float acc = 0.f;
    for (int k = 0; k < D; k++) acc += gm[k] * W_both[k * D + t];
    g_C[t] = 0.25f * (acc + b_all[t] + b_n[t] + b_m[t] + b_both[t]);
}

// ---------------- tensor-core GEMM: out = 0.25*(A@W) [+G[col]+H[row]+C] ------
#define AS_STRIDE 68
#define WS_STRIDE 132
#define SMEM_AS   0
#define SMEM_WS   (128 * AS_STRIDE * 4)
#define SMEM_SC   (SMEM_WS + 64 * WS_STRIDE * 4)
#define SMEM_IC   (SMEM_SC + 128 * 4)
#define SMEM_IR   (SMEM_IC + 128 * 4)
#define SMEM_TOT  (SMEM_IR + 128 * 4)

__device__ __forceinline__ void mma_tf32(float* c, const unsigned* a, unsigned b0, unsigned b1) {
    asm volatile(
        "mma.sync.aligned.m16n8k8.row.col.f32.tf32.tf32.f32 "
        "{%0,%1,%2,%3}, {%4,%5,%6,%7}, {%8,%9}, {%0,%1,%2,%3};"
        : "+f"(c[0]), "+f"(c[1]), "+f"(c[2]), "+f"(c[3])
        : "r"(a[0]), "r"(a[1]), "r"(a[2]), "r"(a[3]), "r"(b0), "r"(b1));
}

template <bool GATHER>
__global__ void __launch_bounds__(256, 2)
gemm_tc(const float* __restrict__ A, const float* __restrict__ W,
        float* __restrict__ out, int M,
        const int* __restrict__ colidx, const int* __restrict__ rowidx) {
    extern __shared__ char smem[];
    float* As = (float*)(smem + SMEM_AS);
    float* Ws = (float*)(smem + SMEM_WS);
    float* sC = (float*)(smem + SMEM_SC);
    int*   sc = (int*)  (smem + SMEM_IC);
    int*   sr = (int*)  (smem + SMEM_IR);

    const int tid  = threadIdx.x;
    const int lane = tid & 31;
    const int wid  = tid >> 5;
    const int g    = lane >> 2;
    const int t    = lane & 3;
    const int mw   = (wid & 3) * 32;
    const int nw   = (wid >> 2) * 64;
    const int m_base = blockIdx.x * 128;

    if (GATHER && tid < 128) {
        int e = m_base + tid;
        if (e >= M) e = M - 1;
        sc[tid] = colidx[e];
        sr[tid] = rowidx[e];
        sC[tid] = g_C[tid];
    }

    float acc[2][8][4];
    #pragma unroll
    for (int f = 0; f < 2; f++)
        #pragma unroll
        for (int nf = 0; nf < 8; nf++)
            #pragma unroll
            for (int i = 0; i < 4; i++) acc[f][nf][i] = 0.f;

    for (int kc = 0; kc < 128; kc += 64) {
        #pragma unroll
        for (int it = 0; it < 8; it++) {
            int i = it * 256 + tid;
            int m = i >> 4, kq = i & 15;
            int row = m_base + m;
            if (row >= M) row = M - 1;
            float4 v = *(const float4*)(A + (size_t)row * 128 + kc + kq * 4);
            unsigned* dst = (unsigned*)(As + m * AS_STRIDE + kq * 4);
            dst[0] = to_tf32(v.x); dst[1] = to_tf32(v.y);
            dst[2] = to_tf32(v.z); dst[3] = to_tf32(v.w);
        }
        #pragma unroll
        for (int it = 0; it < 8; it++) {
            int i = it * 256 + tid;
            int k = i >> 5, nq = i & 31;
            float4 v = *(const float4*)(W + (size_t)(kc + k) * 128 + nq * 4);
            unsigned* dst = (unsigned*)(Ws + k * WS_STRIDE + nq * 4);
            dst[0] = to_tf32(v.x); dst[1] = to_tf32(v.y);
            dst[2] = to_tf32(v.z); dst[3] = to_tf32(v.w);
        }
        __syncthreads();

        #pragma unroll
        for (int ks = 0; ks < 8; ks++) {
            int k0 = ks * 8;
            unsigned a[2][4];
            #pragma unroll
            for (int f = 0; f < 2; f++) {
                const unsigned* ap = (const unsigned*)(As + (mw + f * 16 + g) * AS_STRIDE + k0 + t);
                const unsigned* ap8 = ap + 8 * AS_STRIDE;
                a[f][0] = ap[0];  a[f][1] = ap8[0];
                a[f][2] = ap[4];  a[f][3] = ap8[4];
            }
            #pragma unroll
            for (int nf = 0; nf < 8; nf++) {
                int n = nw + nf * 8 + g;
                unsigned b0 = *(const unsigned*)(Ws + (k0 + t) * WS_STRIDE + n);
                unsigned b1 = *(const unsigned*)(Ws + (k0 + t + 4) * WS_STRIDE + n);
                mma_tf32(acc[0][nf], a[0], b0, b1);
                mma_tf32(acc[1][nf], a[1], b0, b1);
            }
        }
        __syncthreads();
    }

    #pragma unroll
    for (int f = 0; f < 2; f++) {
        #pragma unroll
        for (int nf = 0; nf < 8; nf++) {
            int nb = nw + nf * 8 + 2 * t;
            #pragma unroll
            for (int half = 0; half < 2; half++) {
                int m_loc = mw + f * 16 + g + half * 8;
                int e = m_base + m_loc;
                if (e >= M) continue;
                float2 o;
                o.x = acc[f][nf][half * 2 + 0] * 0.25f;
                o.y = acc[f][nf][half * 2 + 1] * 0.25f;
                if (GATHER) {
                    int c = sc[m_loc], r = sr[m_loc];
                    float2 gv = *(const float2*)(g_G + (size_t)c * 128 + nb);
                    float2 hv = *(const float2*)(g_H + (size_t)r * 128 + nb);
                    o.x += gv.x + hv.x + sC[nb];
                    o.y += gv.y + hv.y + sC[nb + 1];
                }
                *(float2*)(out + (size_t)e * 128 + nb) = o;
            }
        }
    }
}

// ---------------------------------------------------------------------------
extern "C" void kernel_launch(void* const* d_in, const int* in_sizes, int n_in,
                              void* d_out, int out_size) {
    const float* values  = (const float*)d_in[0];
    const int*   row_idx = (const int*)  d_in[1];
    const int*   col_idx = (const int*)  d_in[2];
    const float* W_all   = (const float*)d_in[3];
    const float* b_all   = (const float*)d_in[4];
    const float* W_n     = (const float*)d_in[5];
    const float* b_n     = (const float*)d_in[6];
    const float* W_m     = (const float*)d_in[7];
    const float* b_m     = (const float*)d_in[8];
    const float* W_both  = (const float*)d_in[9];
    const float* b_both  = (const float*)d_in[10];
    float* out = (float*)d_out;

    // one-time host-side resources (no device allocation)
    static cudaStream_t s_row = nullptr;
    static cudaEvent_t ev_fork = nullptr, ev_join = nullptr;
    if (!s_row) {
        cudaStreamCreateWithFlags(&s_row, cudaStreamNonBlocking);
        cudaEventCreateWithFlags(&ev_fork, cudaEventDisableTiming);
        cudaEventCreateWithFlags(&ev_join, cudaEventDisableTiming);
        cudaFuncSetAttribute(gemm_tc<false>, cudaFuncAttributeMaxDynamicSharedMemorySize, SMEM_TOT);
        cudaFuncSetAttribute(gemm_tc<true>,  cudaFuncAttributeMaxDynamicSharedMemorySize, SMEM_TOT);
    }

    float* colmean_p; cudaGetSymbolAddress((void**)&colmean_p, g_colmean);
    float* rowmean_p; cudaGetSymbolAddress((void**)&rowmean_p, g_rowmean);
    float* G_p;       cudaGetSymbolAddress((void**)&G_p, g_G);
    float* H_p;       cudaGetSymbolAddress((void**)&H_p, g_H);
    int* partial_p;   cudaGetSymbolAddress((void**)&partial_p, g_partial);
    int* poff_p;      cudaGetSymbolAddress((void**)&poff_p, g_poff);
    int* rowcnt_p;    cudaGetSymbolAddress((void**)&rowcnt_p, g_rowcnt);
    int* rowoff_p;    cudaGetSymbolAddress((void**)&rowoff_p, g_rowoff);

    // fork: row chain on s_row
    cudaEventRecord(ev_fork, 0);
    cudaStreamWaitEvent(s_row, ev_fork, 0);

    // ---- col chain (default stream) ----
    zero_col_k<<<(MCOLS + 255) / 256, 256>>>();
    hist_col_k<<<(NNZ + 255) / 256, 256>>>(col_idx);
    scan1_k<<<SCAN_BLOCKS, 1024>>>();
    small_scan_k<<<1, 1024>>>(partial_p, poff_p, SCAN_BLOCKS);
    scan3_k<<<SCAN_BLOCKS, 1024>>>();
    scatter_col_k<<<(NNZ + 255) / 256, 256>>>(col_idx);
    colmean_k<<<(MCOLS * 32 + 255) / 256, 256>>>(values);
    gemm_tc<false><<<(MCOLS + 127) / 128, 256, SMEM_TOT>>>(colmean_p, W_n, G_p, MCOLS, nullptr, nullptr);

    // ---- row chain (s_row) ----
    zero_row_k<<<1, 512, 0, s_row>>>();
    hist_row_k<<<148, 256, 0, s_row>>>(row_idx);
    small_scan_k<<<1, 1024, 0, s_row>>>(rowcnt_p, rowoff_p, NROWS);
    scatter_row_k<<<148, 256, 0, s_row>>>(row_idx);
    rowmean_k<<<NROWS, 256, 0, s_row>>>(values);
    cconst_k<<<1, 128, 0, s_row>>>(W_both, b_all, b_n, b_m, b_both);
    gemm_tc<false><<<(NROWS + 127) / 128, 256, SMEM_TOT, s_row>>>(rowmean_p, W_m, H_p, NROWS, nullptr, nullptr);

    // join, then main GEMM
    cudaEventRecord(ev_join, s_row);
    cudaStreamWaitEvent(0, ev_join, 0);
    gemm_tc<true><<<(NNZ + 127) / 128, 256, SMEM_TOT>>>(values, W_all, out, NNZ, col_idx, row_idx);
}

// round 5
// speedup vs baseline: 1.8068x; 1.0052x over previous
#include <cuda_runtime.h>

#define NNZ   1000000
#define NROWS 500
#define MCOLS 50000
#define D     128
#define SCAN_BLOCKS 49   // ceil(50000/1024)

// ---------------- scratch (device globals; no runtime allocation) ----------
__device__ float g_colmean[MCOLS * D];
__device__ float g_rowsum [NROWS * D];
__device__ float g_rowmean[NROWS * D];
__device__ float g_G[MCOLS * D];         // 0.25 * colmean @ W_n
__device__ float g_H[NROWS * D];         // 0.25 * rowmean @ W_m
__device__ float g_C[D];                 // 0.25*(gmean@W_both + all biases)
__device__ int   g_colcnt[MCOLS];
__device__ int   g_rowcnt[NROWS];
__device__ int   g_coloff[MCOLS + 1];
__device__ int   g_rowoff[NROWS + 1];
__device__ int   g_colcur[MCOLS];
__device__ int   g_rowcur[NROWS];
__device__ int   g_colids[NNZ];
__device__ int   g_rowids[NNZ];
__device__ int   g_partial[SCAN_BLOCKS];
__device__ int   g_poff[SCAN_BLOCKS + 1];

__device__ __forceinline__ unsigned to_tf32(float f) {
    unsigned u;
    asm("cvt.rna.tf32.f32 %0, %1;" : "=r"(u) : "f"(f));
    return u;
}

// ---------------- zeroing ----------------------------------------------------
__global__ void zero_col_k() {
    int i = blockIdx.x * blockDim.x + threadIdx.x;
    if (i < MCOLS) { g_colcnt[i] = 0; g_colcur[i] = 0; }
}
__global__ void zero_row_k() {
    int i = threadIdx.x;
    if (i < NROWS) { g_rowcnt[i] = 0; g_rowcur[i] = 0; }
}

// ---------------- histograms -------------------------------------------------
__global__ void hist_col_k(const int* __restrict__ col_idx) {
    int e = blockIdx.x * blockDim.x + threadIdx.x;
    if (e < NNZ) atomicAdd(&g_colcnt[col_idx[e]], 1);
}
__global__ void hist_row_k(const int* __restrict__ row_idx) {  // grid 148
    __shared__ int h[NROWS];
    for (int i = threadIdx.x; i < NROWS; i += blockDim.x) h[i] = 0;
    __syncthreads();
    for (int e = blockIdx.x * blockDim.x + threadIdx.x; e < NNZ;
         e += gridDim.x * blockDim.x)
        atomicAdd(&h[row_idx[e]], 1);
    __syncthreads();
    for (int i = threadIdx.x; i < NROWS; i += blockDim.x) {
        int c = h[i];
        if (c) atomicAdd(&g_rowcnt[i], c);
    }
}

// ---------------- hierarchical column scan -----------------------------------
__global__ void scan1_k() {
    __shared__ int wsum[32];
    int i = blockIdx.x * 1024 + threadIdx.x;
    int lane = threadIdx.x & 31, wid = threadIdx.x >> 5;
    int v = (i < MCOLS) ? g_colcnt[i] : 0;
    #pragma unroll
    for (int off = 16; off > 0; off >>= 1) v += __shfl_down_sync(~0u, v, off);
    if (lane == 0) wsum[wid] = v;
    __syncthreads();
    if (wid == 0) {
        int s = wsum[lane];
        #pragma unroll
        for (int off = 16; off > 0; off >>= 1) s += __shfl_down_sync(~0u, s, off);
        if (lane == 0) g_partial[blockIdx.x] = s;
    }
}

__global__ void small_scan_k(const int* __restrict__ in, int* __restrict__ out, int n) {
    __shared__ int wsum[32];
    int tid = threadIdx.x, lane = tid & 31, wid = tid >> 5;
    int v = (tid < n) ? in[tid] : 0;
    int s = v;
    #pragma unroll
    for (int off = 1; off < 32; off <<= 1) {
        int t = __shfl_up_sync(~0u, s, off);
        if (lane >= off) s += t;
    }
    if (lane == 31) wsum[wid] = s;
    __syncthreads();
    if (wid == 0) {
        int ws = wsum[lane];
        #pragma unroll
        for (int off = 1; off < 32; off <<= 1) {
            int t = __shfl_up_sync(~0u, ws, off);
            if (lane >= off) ws += t;
        }
        wsum[lane] = ws;
    }
    __syncthreads();
    int excl = s - v + (wid > 0 ? wsum[wid - 1] : 0);
    if (tid < n) out[tid] = excl;
    if (tid == n - 1) out[n] = excl + v;
}

__global__ void scan3_k() {
    __shared__ int wsum[32];
    int i = blockIdx.x * 1024 + threadIdx.x;
    int lane = threadIdx.x & 31, wid = threadIdx.x >> 5;
    int v = (i < MCOLS) ? g_colcnt[i] : 0;
    int s = v;
    #pragma unroll
    for (int off = 1; off < 32; off <<= 1) {
        int t = __shfl_up_sync(~0u, s, off);
        if (lane >= off) s += t;
    }
    if (lane == 31) wsum[wid] = s;
    __syncthreads();
    if (wid == 0) {
        int ws = wsum[lane];
        #pragma unroll
        for (int off = 1; off < 32; off <<= 1) {
            int t = __shfl_up_sync(~0u, ws, off);
            if (lane >= off) ws += t;
        }
        wsum[lane] = ws;
    }
    __syncthreads();
    int excl = s - v + (wid > 0 ? wsum[wid - 1] : 0) + g_poff[blockIdx.x];
    if (i < MCOLS) g_coloff[i] = excl;
    if (i == MCOLS - 1) g_coloff[MCOLS] = excl + v;
}

// ---------------- scatters ---------------------------------------------------
__global__ void scatter_col_k(const int* __restrict__ col_idx) {
    int e = blockIdx.x * blockDim.x + threadIdx.x;
    if (e < NNZ) {
        int c = col_idx[e];
        int p = atomicAdd(&g_colcur[c], 1);
        g_colids[g_coloff[c] + p] = e;
    }
}
__global__ void scatter_row_k(const int* __restrict__ row_idx) {  // grid 148
    __shared__ int lcnt[NROWS];
    __shared__ int lbase[NROWS];
    const int tid = threadIdx.x;
    const int chunk = (NNZ + gridDim.x - 1) / gridDim.x;
    const int lo = blockIdx.x * chunk;
    const int hi = (lo + chunk < NNZ) ? lo + chunk : NNZ;

    for (int i = tid; i < NROWS; i += blockDim.x) lcnt[i] = 0;
    __syncthreads();
    for (int e = lo + tid; e < hi; e += blockDim.x)
        atomicAdd(&lcnt[row_idx[e]], 1);
    __syncthreads();
    for (int i = tid; i < NROWS; i += blockDim.x) {
        int c = lcnt[i];
        int b = c ? atomicAdd(&g_rowcur[i], c) : 0;
        lbase[i] = g_rowoff[i] + b;
        lcnt[i] = 0;
    }
    __syncthreads();
    for (int e = lo + tid; e < hi; e += blockDim.x) {
        int r = row_idx[e];
        int slot = atomicAdd(&lcnt[r], 1);
        g_rowids[lbase[r] + slot] = e;
    }
}

// ---------------- means ------------------------------------------------------
__global__ void colmean_k(const float* __restrict__ values) {
    int warp = (blockIdx.x * blockDim.x + threadIdx.x) >> 5;
    int lane = threadIdx.x & 31;
    if (warp >= MCOLS) return;
    int beg = g_coloff[warp], end = g_coloff[warp + 1];
    float4 acc = make_float4(0.f, 0.f, 0.f, 0.f);
    int j = beg;
    // unrolled-by-4 (MLP=4 on the value-row loads)
    for (; j + 4 <= end; j += 4) {
        int e0 = g_colids[j], e1 = g_colids[j + 1];
        int e2 = g_colids[j + 2], e3 = g_colids[j + 3];
        float4 v0 = *(const float4*)(values + (size_t)e0 * D + lane * 4);
        float4 v1 = *(const float4*)(values + (size_t)e1 * D + lane * 4);
        float4 v2 = *(const float4*)(values + (size_t)e2 * D + lane * 4);
        float4 v3 = *(const float4*)(values + (size_t)e3 * D + lane * 4);
        acc.x += (v0.x + v1.x) + (v2.x + v3.x);
        acc.y += (v0.y + v1.y) + (v2.y + v3.y);
        acc.z += (v0.z + v1.z) + (v2.z + v3.z);
        acc.w += (v0.w + v1.w) + (v2.w + v3.w);
    }
    for (; j < end; j++) {
        int e = g_colids[j];
        float4 v = *(const float4*)(values + (size_t)e * D + lane * 4);
        acc.x += v.x; acc.y += v.y; acc.z += v.z; acc.w += v.w;
    }
    int n = end - beg;
    float inv = 1.0f / (float)(n > 1 ? n : 1);
    acc.x *= inv; acc.y *= inv; acc.z *= inv; acc.w *= inv;
    *(float4*)(g_colmean + (size_t)warp * D + lane * 4) = acc;
}

__global__ void rowmean_k(const float* __restrict__ values) {
    int r = blockIdx.x;
    int lane = threadIdx.x & 31, w = threadIdx.x >> 5;  // 8 warps
    int beg = g_rowoff[r], end = g_rowoff[r + 1];
    float4 acc = make_float4(0.f, 0.f, 0.f, 0.f);
    for (int j = beg + w; j < end; j += 8) {
        int e = g_rowids[j];
        float4 v = *(const float4*)(values + (size_t)e * D + lane * 4);
        acc.x += v.x; acc.y += v.y; acc.z += v.z; acc.w += v.w;
    }
    __shared__ float4 s[8][32];
    s[w][lane] = acc;
    __syncthreads();
    if (w == 0) {
        #pragma unroll
        for (int k = 1; k < 8; k++) {
            float4 t = s[k][lane];
            acc.x += t.x; acc.y += t.y; acc.z += t.z; acc.w += t.w;
        }
        *(float4*)(g_rowsum + (size_t)r * D + lane * 4) = acc;
        int n = end - beg;
        float inv = 1.0f / (float)(n > 1 ? n : 1);
        acc.x *= inv; acc.y *= inv; acc.z *= inv; acc.w *= inv;
        *(float4*)(g_rowmean + (size_t)r * D + lane * 4) = acc;
    }
}

// ---------------- global-mean + fused constant -------------------------------
__global__ void cconst_k(const float* __restrict__ W_both,
                         const float* __restrict__ b_all, const float* __restrict__ b_n,
                         const float* __restrict__ b_m,  const float* __restrict__ b_both) {
    __shared__ float gm[D];
    int t = threadIdx.x;
    float s = 0.f;
    for (int r = 0; r < NROWS; r++) s += g_rowsum[r * D + t];
    gm[t] = s * (1.0f / (float)NNZ);
    __syncthreads();
    float acc = 0.f;
    for (int k = 0; k < D; k++) acc += gm[k] * W_both[k * D + t];
    g_C[t] = 0.25f * (acc + b_all[t] + b_n[t] + b_m[t] + b_both[t]);
}

// ---------------- tensor-core GEMM: out = 0.25*(A@W) [+G[col]+H[row]+C] ------
#define AS_STRIDE 68
#define WS_STRIDE 132
#define SMEM_AS   0
#define SMEM_WS   (128 * AS_STRIDE * 4)
#define SMEM_SC   (SMEM_WS + 64 * WS_STRIDE * 4)
#define SMEM_IC   (SMEM_SC + 128 * 4)
#define SMEM_IR   (SMEM_IC + 128 * 4)
#define SMEM_TOT  (SMEM_IR + 128 * 4)

__device__ __forceinline__ void mma_tf32(float* c, const unsigned* a, unsigned b0, unsigned b1) {
    asm volatile(
        "mma.sync.aligned.m16n8k8.row.col.f32.tf32.tf32.f32 "
        "{%0,%1,%2,%3}, {%4,%5,%6,%7}, {%8,%9}, {%0,%1,%2,%3};"
        : "+f"(c[0]), "+f"(c[1]), "+f"(c[2]), "+f"(c[3])
        : "r"(a[0]), "r"(a[1]), "r"(a[2]), "r"(a[3]), "r"(b0), "r"(b1));
}

template <bool GATHER>
__global__ void __launch_bounds__(256, 2)
gemm_tc(const float* __restrict__ A, const float* __restrict__ W,
        float* __restrict__ out, int M,
        const int* __restrict__ colidx, const int* __restrict__ rowidx) {
    extern __shared__ char smem[];
    float* As = (float*)(smem + SMEM_AS);
    float* Ws = (float*)(smem + SMEM_WS);
    float* sC = (float*)(smem + SMEM_SC);
    int*   sc = (int*)  (smem + SMEM_IC);
    int*   sr = (int*)  (smem + SMEM_IR);

    const int tid  = threadIdx.x;
    const int lane = tid & 31;
    const int wid  = tid >> 5;
    const int g    = lane >> 2;
    const int t    = lane & 3;
    const int mw   = (wid & 3) * 32;
    const int nw   = (wid >> 2) * 64;
    const int m_base = blockIdx.x * 128;

    if (GATHER && tid < 128) {
        int e = m_base + tid;
        if (e >= M) e = M - 1;
        sc[tid] = colidx[e];
        sr[tid] = rowidx[e];
        sC[tid] = g_C[tid];
    }

    float acc[2][8][4];
    #pragma unroll
    for (int f = 0; f < 2; f++)
        #pragma unroll
        for (int nf = 0; nf < 8; nf++)
            #pragma unroll
            for (int i = 0; i < 4; i++) acc[f][nf][i] = 0.f;

    for (int kc = 0; kc < 128; kc += 64) {
        #pragma unroll
        for (int it = 0; it < 8; it++) {
            int i = it * 256 + tid;
            int m = i >> 4, kq = i & 15;
            int row = m_base + m;
            if (row >= M) row = M - 1;
            float4 v = *(const float4*)(A + (size_t)row * 128 + kc + kq * 4);
            unsigned* dst = (unsigned*)(As + m * AS_STRIDE + kq * 4);
            dst[0] = to_tf32(v.x); dst[1] = to_tf32(v.y);
            dst[2] = to_tf32(v.z); dst[3] = to_tf32(v.w);
        }
        #pragma unroll
        for (int it = 0; it < 8; it++) {
            int i = it * 256 + tid;
            int k = i >> 5, nq = i & 31;
            float4 v = *(const float4*)(W + (size_t)(kc + k) * 128 + nq * 4);
            unsigned* dst = (unsigned*)(Ws + k * WS_STRIDE + nq * 4);
            dst[0] = to_tf32(v.x); dst[1] = to_tf32(v.y);
            dst[2] = to_tf32(v.z); dst[3] = to_tf32(v.w);
        }
        __syncthreads();

        #pragma unroll
        for (int ks = 0; ks < 8; ks++) {
            int k0 = ks * 8;
            unsigned a[2][4];
            #pragma unroll
            for (int f = 0; f < 2; f++) {
                const unsigned* ap = (const unsigned*)(As + (mw + f * 16 + g) * AS_STRIDE + k0 + t);
                const unsigned* ap8 = ap + 8 * AS_STRIDE;
                a[f][0] = ap[0];  a[f][1] = ap8[0];
                a[f][2] = ap[4];  a[f][3] = ap8[4];
            }
            #pragma unroll
            for (int nf = 0; nf < 8; nf++) {
                int n = nw + nf * 8 + g;
                unsigned b0 = *(const unsigned*)(Ws + (k0 + t) * WS_STRIDE + n);
                unsigned b1 = *(const unsigned*)(Ws + (k0 + t + 4) * WS_STRIDE + n);
                mma_tf32(acc[0][nf], a[0], b0, b1);
                mma_tf32(acc[1][nf], a[1], b0, b1);
            }
        }
        __syncthreads();
    }

    #pragma unroll
    for (int f = 0; f < 2; f++) {
        #pragma unroll
        for (int nf = 0; nf < 8; nf++) {
            int nb = nw + nf * 8 + 2 * t;
            #pragma unroll
            for (int half = 0; half < 2; half++) {
                int m_loc = mw + f * 16 + g + half * 8;
                int e = m_base + m_loc;
                if (e >= M) continue;
                float2 o;
                o.x = acc[f][nf][half * 2 + 0] * 0.25f;
                o.y = acc[f][nf][half * 2 + 1] * 0.25f;
                if (GATHER) {
                    int c = sc[m_loc], r = sr[m_loc];
                    float2 gv = *(const float2*)(g_G + (size_t)c * 128 + nb);
                    float2 hv = *(const float2*)(g_H + (size_t)r * 128 + nb);
                    o.x += gv.x + hv.x + sC[nb];
                    o.y += gv.y + hv.y + sC[nb + 1];
                }
                *(float2*)(out + (size_t)e * 128 + nb) = o;
            }
        }
    }
}

// ---------------------------------------------------------------------------
extern "C" void kernel_launch(void* const* d_in, const int* in_sizes, int n_in,
                              void* d_out, int out_size) {
    const float* values  = (const float*)d_in[0];
    const int*   row_idx = (const int*)  d_in[1];
    const int*   col_idx = (const int*)  d_in[2];
    const float* W_all   = (const float*)d_in[3];
    const float* b_all   = (const float*)d_in[4];
    const float* W_n     = (const float*)d_in[5];
    const float* b_n     = (const float*)d_in[6];
    const float* W_m     = (const float*)d_in[7];
    const float* b_m     = (const float*)d_in[8];
    const float* W_both  = (const float*)d_in[9];
    const float* b_both  = (const float*)d_in[10];
    float* out = (float*)d_out;

    // one-time host-side resources (no device allocation)
    static cudaStream_t s_col = nullptr, s_row = nullptr;
    static cudaEvent_t ev_fork = nullptr, ev_jc = nullptr, ev_jr = nullptr;
    if (!s_col) {
        cudaStreamCreateWithFlags(&s_col, cudaStreamNonBlocking);
        cudaStreamCreateWithFlags(&s_row, cudaStreamNonBlocking);
        cudaEventCreateWithFlags(&ev_fork, cudaEventDisableTiming);
        cudaEventCreateWithFlags(&ev_jc, cudaEventDisableTiming);
        cudaEventCreateWithFlags(&ev_jr, cudaEventDisableTiming);
        cudaFuncSetAttribute(gemm_tc<false>, cudaFuncAttributeMaxDynamicSharedMemorySize, SMEM_TOT);
        cudaFuncSetAttribute(gemm_tc<true>,  cudaFuncAttributeMaxDynamicSharedMemorySize, SMEM_TOT);
    }

    float* colmean_p; cudaGetSymbolAddress((void**)&colmean_p, g_colmean);
    float* rowmean_p; cudaGetSymbolAddress((void**)&rowmean_p, g_rowmean);
    float* G_p;       cudaGetSymbolAddress((void**)&G_p, g_G);
    float* H_p;       cudaGetSymbolAddress((void**)&H_p, g_H);
    int* partial_p;   cudaGetSymbolAddress((void**)&partial_p, g_partial);
    int* poff_p;      cudaGetSymbolAddress((void**)&poff_p, g_poff);
    int* rowcnt_p;    cudaGetSymbolAddress((void**)&rowcnt_p, g_rowcnt);
    int* rowoff_p;    cudaGetSymbolAddress((void**)&rowoff_p, g_rowoff);

    // fork: both chains on non-blocking streams (NOTHING else on stream 0,
    // so legacy-stream implicit sync cannot serialize the branches)
    cudaEventRecord(ev_fork, 0);
    cudaStreamWaitEvent(s_col, ev_fork, 0);
    cudaStreamWaitEvent(s_row, ev_fork, 0);

    // ---- col chain (s_col) ----
    zero_col_k<<<(MCOLS + 255) / 256, 256, 0, s_col>>>();
    hist_col_k<<<(NNZ + 255) / 256, 256, 0, s_col>>>(col_idx);
    scan1_k<<<SCAN_BLOCKS, 1024, 0, s_col>>>();
    small_scan_k<<<1, 1024, 0, s_col>>>(partial_p, poff_p, SCAN_BLOCKS);
    scan3_k<<<SCAN_BLOCKS, 1024, 0, s_col>>>();
    scatter_col_k<<<(NNZ + 255) / 256, 256, 0, s_col>>>(col_idx);
    colmean_k<<<(MCOLS * 32 + 255) / 256, 256, 0, s_col>>>(values);
    gemm_tc<false><<<(MCOLS + 127) / 128, 256, SMEM_TOT, s_col>>>(colmean_p, W_n, G_p, MCOLS, nullptr, nullptr);

    // ---- row chain (s_row) ----
    zero_row_k<<<1, 512, 0, s_row>>>();
    hist_row_k<<<148, 256, 0, s_row>>>(row_idx);
    small_scan_k<<<1, 1024, 0, s_row>>>(rowcnt_p, rowoff_p, NROWS);
    scatter_row_k<<<148, 256, 0, s_row>>>(row_idx);
    rowmean_k<<<NROWS, 256, 0, s_row>>>(values);
    cconst_k<<<1, 128, 0, s_row>>>(W_both, b_all, b_n, b_m, b_both);
    gemm_tc<false><<<(NROWS + 127) / 128, 256, SMEM_TOT, s_row>>>(rowmean_p, W_m, H_p, NROWS, nullptr, nullptr);

    // join both into stream 0, then main GEMM
    cudaEventRecord(ev_jc, s_col);
    cudaEventRecord(ev_jr, s_row);
    cudaStreamWaitEvent(0, ev_jc, 0);
    cudaStreamWaitEvent(0, ev_jr, 0);
    gemm_tc<true><<<(NNZ + 127) / 128, 256, SMEM_TOT>>>(values, W_all, out, NNZ, col_idx, row_idx);
}